// round 9
// baseline (speedup 1.0000x reference)
#include <cuda_runtime.h>
#include <cuda_bf16.h>
#include <math_constants.h>
#include <cstdint>

#define BATCH 4096
#define DIM 256
#define NEG_INF (-CUDART_INF_F)

// ---------------- static scratch ----------------
__device__ __nv_bfloat16 g_ab[BATCH * DIM];    // normalized bf16
__device__ __nv_bfloat16 g_p0b[BATCH * DIM];
__device__ __nv_bfloat16 g_p1b[BATCH * DIM];
__device__ float g_posdot[2][BATCH];
__device__ unsigned g_maxbits[2][BATCH];

// ---------------- helpers ----------------
__device__ __forceinline__ unsigned enc_f(float f) {
    unsigned u = __float_as_uint(f);
    return (u & 0x80000000u) ? ~u : (u | 0x80000000u);
}
__device__ __forceinline__ float dec_f(unsigned u) {
    u = (u & 0x80000000u) ? (u & 0x7FFFFFFFu) : ~u;
    return __uint_as_float(u);
}
__device__ __forceinline__ uint32_t smem_u32(const void* p) {
    uint32_t a;
    asm("{ .reg .u64 t; cvta.to.shared.u64 t, %1; cvt.u32.u64 %0, t; }" : "=r"(a) : "l"(p));
    return a;
}
__device__ __forceinline__ void cp_async16(uint32_t dst, const void* src) {
    asm volatile("cp.async.cg.shared.global [%0], [%1], 16;" :: "r"(dst), "l"(src) : "memory");
}
#define CP_COMMIT() asm volatile("cp.async.commit_group;" ::: "memory")
#define CP_WAIT1()  asm volatile("cp.async.wait_group 1;" ::: "memory")

__device__ __forceinline__ void ldsm_x4(uint32_t& r0, uint32_t& r1, uint32_t& r2, uint32_t& r3,
                                        uint32_t addr) {
    asm volatile("ldmatrix.sync.aligned.m8n8.x4.shared.b16 {%0,%1,%2,%3}, [%4];"
                 : "=r"(r0), "=r"(r1), "=r"(r2), "=r"(r3) : "r"(addr));
}
__device__ __forceinline__ void mma16816(float* c, const uint32_t* a, const uint32_t* b) {
    asm volatile(
        "mma.sync.aligned.m16n8k16.row.col.f32.bf16.bf16.f32 "
        "{%0,%1,%2,%3}, {%4,%5,%6,%7}, {%8,%9}, {%0,%1,%2,%3};"
        : "+f"(c[0]), "+f"(c[1]), "+f"(c[2]), "+f"(c[3])
        : "r"(a[0]), "r"(a[1]), "r"(a[2]), "r"(a[3]), "r"(b[0]), "r"(b[1]));
}

// ---------------- kernel 1: fused normalize + positive dots ----------------
// One WARP per batch row (shfl-only reduction, no block syncs).
// 256-thread blocks, 8 rows/block, grid 512.
__global__ __launch_bounds__(256) void norm_kernel(const float* __restrict__ anchor,
                                                   const float* __restrict__ positive) {
    int warp = threadIdx.x >> 5, lane = threadIdx.x & 31;
    int i = blockIdx.x * 8 + warp;
    const float4* A  = (const float4*)(anchor   + (size_t)i * DIM);
    const float4* P0 = (const float4*)(positive + (size_t)i * 2 * DIM);
    const float4* P1 = (const float4*)(positive + (size_t)i * 2 * DIM + DIM);

    float4 a0 = A[lane],  a1 = A[lane + 32];
    float4 b0 = P0[lane], b1 = P0[lane + 32];
    float4 c0 = P1[lane], c1 = P1[lane + 32];

    float sa = a0.x*a0.x + a0.y*a0.y + a0.z*a0.z + a0.w*a0.w
             + a1.x*a1.x + a1.y*a1.y + a1.z*a1.z + a1.w*a1.w;
    float s0 = b0.x*b0.x + b0.y*b0.y + b0.z*b0.z + b0.w*b0.w
             + b1.x*b1.x + b1.y*b1.y + b1.z*b1.z + b1.w*b1.w;
    float s1 = c0.x*c0.x + c0.y*c0.y + c0.z*c0.z + c0.w*c0.w
             + c1.x*c1.x + c1.y*c1.y + c1.z*c1.z + c1.w*c1.w;
    float d0 = a0.x*b0.x + a0.y*b0.y + a0.z*b0.z + a0.w*b0.w
             + a1.x*b1.x + a1.y*b1.y + a1.z*b1.z + a1.w*b1.w;
    float d1 = a0.x*c0.x + a0.y*c0.y + a0.z*c0.z + a0.w*c0.w
             + a1.x*c1.x + a1.y*c1.y + a1.z*c1.z + a1.w*c1.w;
#pragma unroll
    for (int o = 16; o; o >>= 1) {
        sa += __shfl_xor_sync(0xffffffffu, sa, o);
        s0 += __shfl_xor_sync(0xffffffffu, s0, o);
        s1 += __shfl_xor_sync(0xffffffffu, s1, o);
        d0 += __shfl_xor_sync(0xffffffffu, d0, o);
        d1 += __shfl_xor_sync(0xffffffffu, d1, o);
    }
    float ia = 1.0f / fmaxf(sqrtf(sa), 1e-12f);
    float i0 = 1.0f / fmaxf(sqrtf(s0), 1e-12f);
    float i1 = 1.0f / fmaxf(sqrtf(s1), 1e-12f);

    if (lane == 0) {
        g_posdot[0][i] = d0 * ia * i0;
        g_posdot[1][i] = d1 * ia * i1;
        g_maxbits[0][i] = 0u;
        g_maxbits[1][i] = 0u;
    }

    auto pack8 = [](float4 u, float4 v, float s) {
        uint4 o;
        __nv_bfloat162 t;
        t = __floats2bfloat162_rn(u.x * s, u.y * s); o.x = *(uint32_t*)&t;
        t = __floats2bfloat162_rn(u.z * s, u.w * s); o.y = *(uint32_t*)&t;
        t = __floats2bfloat162_rn(v.x * s, v.y * s); o.z = *(uint32_t*)&t;
        t = __floats2bfloat162_rn(v.z * s, v.w * s); o.w = *(uint32_t*)&t;
        return o;
    };
    // interleave: thread writes elems [8*lane, 8*lane+8) -> but a0 is [4*lane],
    // a1 is [4*lane+128]. Write them to their own positions as two uint2s.
    uint4 pa = pack8(a0, a1, ia);
    uint4 p0k = pack8(b0, b1, i0);
    uint4 p1k = pack8(c0, c1, i1);
    uint2* da = (uint2*)(g_ab  + (size_t)i * DIM);
    uint2* dp0 = (uint2*)(g_p0b + (size_t)i * DIM);
    uint2* dp1 = (uint2*)(g_p1b + (size_t)i * DIM);
    da[lane]       = make_uint2(pa.x, pa.y);
    da[lane + 32]  = make_uint2(pa.z, pa.w);
    dp0[lane]      = make_uint2(p0k.x, p0k.y);
    dp0[lane + 32] = make_uint2(p0k.z, p0k.w);
    dp1[lane]      = make_uint2(p1k.x, p1k.y);
    dp1[lane + 32] = make_uint2(p1k.z, p1k.w);
}

// ---------------- kernel 2: bf16 mma.sync GEMM + masked max ----------------
// CTA tile 128x128, 8 warps (2 m x 4 n), warp tile 64x32, K chunks of 64,
// 3-stage cp.async pipeline (ONE sync per chunk), kb^(row&7) swizzle.
// Compact 1-D grid of 2576 blocks:
//   [0,1024)     src1 dense, [1024,2048) src2 dense,
//   [2048,2576)  src0 upper triangle (ctile >= rtile), col-fold for ctile>rtile.
#define TILE 128
#define CHUNK_BYTES (128 * 128)
#define SM_LABC 0
#define SM_LABR 512
#define SM_MAXR 1024
#define SM_MAXC 1536
#define SM_BUF  2048
#define SM_TOTAL (SM_BUF + 6 * CHUNK_BYTES)   // 100352

__global__ __launch_bounds__(256, 2) void gemm_max_kernel(const int* __restrict__ labels) {
    int bid = blockIdx.x;
    int src, rtile, ctile;
    if (bid < 2048) {
        src = 1 + (bid >> 10);
        int t = bid & 1023;
        rtile = t >> 5;
        ctile = t & 31;
    } else {
        src = 0;
        int t = bid - 2048;                     // 0..527, upper triangle
        int r = (int)(32.5f - sqrtf(1056.25f - 2.0f * (float)t));
        while (32 * r - r * (r - 1) / 2 > t) r--;
        while (32 * (r + 1) - (r + 1) * r / 2 <= t) r++;
        rtile = r;
        ctile = r + (t - (32 * r - r * (r - 1) / 2));
    }
    bool colfold = (src == 0) && (ctile > rtile);

    extern __shared__ char smem[];
    uint32_t smem_base = smem_u32(smem);
    int tid = threadIdx.x;
    int wid = tid >> 5, lane = tid & 31;
    int wm = wid >> 2;                 // 0..1
    int wn = wid & 3;                  // 0..3

    int colbase = ctile * TILE;
    int row0 = rtile * TILE;
    const __nv_bfloat16* Bmat = (src == 0) ? g_ab : (src == 1 ? g_p0b : g_p1b);

    if (tid < TILE) {
        *(int*)(smem + SM_LABC + tid * 4) = labels[colbase + tid];
        *(int*)(smem + SM_LABR + tid * 4) = labels[row0 + tid];
        *(unsigned*)(smem + SM_MAXR + tid * 4) = 0u;
        *(unsigned*)(smem + SM_MAXC + tid * 4) = 0u;
    }

    const char* gA = (const char*)(g_ab + (size_t)row0 * DIM);
    const char* gB = (const char*)(Bmat + (size_t)colbase * DIM);

    auto load_stage = [&](int s, int kc) {
        uint32_t abase = smem_base + SM_BUF + s * (2 * CHUNK_BYTES);
        uint32_t bbase = abase + CHUNK_BYTES;
#pragma unroll
        for (int i = 0; i < 4; i++) {
            int id = tid + i * 256;
            int row = id >> 3, kb = id & 7;
            uint32_t off = row * 128 + ((kb ^ (row & 7)) << 4);
            cp_async16(abase + off, gA + row * 512 + kc * 128 + kb * 16);
        }
#pragma unroll
        for (int i = 0; i < 4; i++) {
            int id = tid + i * 256;
            int row = id >> 3, kb = id & 7;
            uint32_t off = row * 128 + ((kb ^ (row & 7)) << 4);
            cp_async16(bbase + off, gB + row * 512 + kc * 128 + kb * 16);
        }
    };

    float acc[4][4][4];
#pragma unroll
    for (int i = 0; i < 4; i++)
#pragma unroll
        for (int j = 0; j < 4; j++)
#pragma unroll
            for (int k = 0; k < 4; k++) acc[i][j][k] = 0.f;

    int arow_lo = wm * 64 + (lane & 15);
    int brow_lo = wn * 32 + (lane & 7) + ((lane >> 4) << 3);
    int a_kb_lo = lane >> 4;
    int b_kb_lo = (lane >> 3) & 1;

    // 3-stage prologue: stages 0,1 for chunks 0,1
    load_stage(0, 0);
    CP_COMMIT();
    load_stage(1, 1);
    CP_COMMIT();

#pragma unroll
    for (int kc = 0; kc < 4; kc++) {
        CP_WAIT1();                     // group kc complete (kc+1 may be pending)
        __syncthreads();                // releases stage (kc-1)%3 AND orders waited data
        if (kc < 2) load_stage((kc + 2) % 3, kc + 2);
        CP_COMMIT();                    // commit every iter to keep group count uniform

        uint32_t abase = smem_base + SM_BUF + (kc % 3) * (2 * CHUNK_BYTES);
        uint32_t bbase = abase + CHUNK_BYTES;
#pragma unroll
        for (int ks = 0; ks < 4; ks++) {
            uint32_t a[4][4];
            int akb = 2 * ks + a_kb_lo;
#pragma unroll
            for (int mf = 0; mf < 4; mf++) {
                int row = arow_lo + mf * 16;
                uint32_t addr = abase + row * 128 + ((akb ^ (row & 7)) << 4);
                ldsm_x4(a[mf][0], a[mf][1], a[mf][2], a[mf][3], addr);
            }
            uint32_t b[4][2];
            int bkb = 2 * ks + b_kb_lo;
#pragma unroll
            for (int nf2 = 0; nf2 < 2; nf2++) {
                int row = brow_lo + nf2 * 16;
                uint32_t addr = bbase + row * 128 + ((bkb ^ (row & 7)) << 4);
                uint32_t r0, r1, r2, r3;
                ldsm_x4(r0, r1, r2, r3, addr);
                b[nf2 * 2][0] = r0; b[nf2 * 2][1] = r1;
                b[nf2 * 2 + 1][0] = r2; b[nf2 * 2 + 1][1] = r3;
            }
#pragma unroll
            for (int mf = 0; mf < 4; mf++)
#pragma unroll
                for (int nfi = 0; nfi < 4; nfi++)
                    mma16816(acc[mf][nfi], a[mf], b[nfi]);
        }
    }
    __syncthreads();   // guard smem label/max region vs last-stage reads

    // ---- epilogue ----
    int g = lane >> 2, tg = lane & 3;
    const int* labC = (const int*)(smem + SM_LABC);
    const int* labR = (const int*)(smem + SM_LABR);
    unsigned* smaxr = (unsigned*)(smem + SM_MAXR);
    unsigned* smaxc = (unsigned*)(smem + SM_MAXC);

    // row-fold: masked max over this warp's 32 columns, per row
#pragma unroll
    for (int mf = 0; mf < 4; mf++) {
#pragma unroll
        for (int h = 0; h < 2; h++) {
            int row = wm * 64 + mf * 16 + g + h * 8;
            int rl = labR[row];
            float m = NEG_INF;
#pragma unroll
            for (int nfi = 0; nfi < 4; nfi++) {
                int col = wn * 32 + nfi * 8 + 2 * tg;
                if (labC[col] != rl)     m = fmaxf(m, acc[mf][nfi][h * 2 + 0]);
                if (labC[col + 1] != rl) m = fmaxf(m, acc[mf][nfi][h * 2 + 1]);
            }
            atomicMax(&smaxr[row], enc_f(m));
        }
    }

    // col-fold (mirror of symmetric tiles): masked max over this warp's 64 rows, per col
    if (colfold) {
#pragma unroll
        for (int nfi = 0; nfi < 4; nfi++) {
#pragma unroll
            for (int cpos = 0; cpos < 2; cpos++) {
                int col = wn * 32 + nfi * 8 + 2 * tg + cpos;
                int cl = labC[col];
                float m = NEG_INF;
#pragma unroll
                for (int mf = 0; mf < 4; mf++) {
#pragma unroll
                    for (int h = 0; h < 2; h++) {
                        int row = wm * 64 + mf * 16 + g + h * 8;
                        if (labR[row] != cl) m = fmaxf(m, acc[mf][nfi][h * 2 + cpos]);
                    }
                }
#pragma unroll
                for (int o = 4; o < 32; o <<= 1) m = fmaxf(m, __shfl_xor_sync(0xffffffffu, m, o));
                if (g == 0) atomicMax(&smaxc[col], enc_f(m));
            }
        }
    }

    __syncthreads();
    if (tid < TILE) {
        unsigned e = smaxr[tid];
        int grow = row0 + tid;
        if (src == 0) {
            atomicMax(&g_maxbits[0][grow], e);
            atomicMax(&g_maxbits[1][grow], e);
            if (colfold) {
                unsigned ec = smaxc[tid];
                int gcol = colbase + tid;
                atomicMax(&g_maxbits[0][gcol], ec);
                atomicMax(&g_maxbits[1][gcol], ec);
            }
        } else {
            atomicMax(&g_maxbits[src - 1][grow], e);
        }
    }
}

// ---------------- kernel 3: fused loss + reduction (single block) ----------------
__global__ void loss_kernel(float* __restrict__ out) {
    int tid = threadIdx.x;                 // 0..1023
    float s = 0.f;
#pragma unroll
    for (int k = 0; k < 8; k++) {
        int idx = tid + k * 1024;
        int v = idx >> 12;
        int i = idx & (BATCH - 1);
        float pd = g_posdot[v][i];
        float nd = dec_f(g_maxbits[v][i]);
        float pos = sqrtf(fmaxf(2.0f - 2.0f * pd, 1e-12f));
        float neg = sqrtf(fmaxf(2.0f - 2.0f * nd, 1e-12f));
        s += fmaxf(pos - neg + 1.0f, 0.0f);
    }
#pragma unroll
    for (int o = 16; o; o >>= 1) s += __shfl_down_sync(0xffffffffu, s, o);
    __shared__ float ws[32];
    if ((tid & 31) == 0) ws[tid >> 5] = s;
    __syncthreads();
    if (tid < 32) {
        float t = ws[tid];
#pragma unroll
        for (int o = 16; o; o >>= 1) t += __shfl_down_sync(0xffffffffu, t, o);
        if (tid == 0) out[0] = t * (1.0f / 8192.0f);
    }
}

// ---------------------------------------------------------------------------
extern "C" void kernel_launch(void* const* d_in, const int* in_sizes, int n_in,
                              void* d_out, int out_size) {
    const float* anchor = (const float*)d_in[0];
    const float* positive = (const float*)d_in[1];
    const int* labels = (const int*)d_in[2];

    cudaFuncSetAttribute(gemm_max_kernel, cudaFuncAttributeMaxDynamicSharedMemorySize, SM_TOTAL);

    norm_kernel<<<512, 256>>>(anchor, positive);
    gemm_max_kernel<<<2576, 256, SM_TOTAL>>>(labels);
    loss_kernel<<<1, 1024>>>((float*)d_out);
}

// round 10
// speedup vs baseline: 1.4938x; 1.4938x over previous
#include <cuda_runtime.h>
#include <cuda_bf16.h>
#include <math_constants.h>
#include <cstdint>

#define BATCH 4096
#define DIM 256
#define NEG_INF (-CUDART_INF_F)

// ---------------- static scratch ----------------
__device__ __nv_bfloat16 g_ab[BATCH * DIM];    // normalized bf16
__device__ __nv_bfloat16 g_p0b[BATCH * DIM];
__device__ __nv_bfloat16 g_p1b[BATCH * DIM];
__device__ float g_posdot[2][BATCH];
__device__ unsigned g_maxbits[2][BATCH];

// ---------------- helpers ----------------
__device__ __forceinline__ unsigned enc_f(float f) {
    unsigned u = __float_as_uint(f);
    return (u & 0x80000000u) ? ~u : (u | 0x80000000u);
}
__device__ __forceinline__ float dec_f(unsigned u) {
    u = (u & 0x80000000u) ? (u & 0x7FFFFFFFu) : ~u;
    return __uint_as_float(u);
}
__device__ __forceinline__ uint32_t smem_u32(const void* p) {
    uint32_t a;
    asm("{ .reg .u64 t; cvta.to.shared.u64 t, %1; cvt.u32.u64 %0, t; }" : "=r"(a) : "l"(p));
    return a;
}
__device__ __forceinline__ void cp_async16(uint32_t dst, const void* src) {
    asm volatile("cp.async.cg.shared.global [%0], [%1], 16;" :: "r"(dst), "l"(src) : "memory");
}
#define CP_COMMIT() asm volatile("cp.async.commit_group;" ::: "memory")
#define CP_WAIT1()  asm volatile("cp.async.wait_group 1;" ::: "memory")

__device__ __forceinline__ void ldsm_x4(uint32_t& r0, uint32_t& r1, uint32_t& r2, uint32_t& r3,
                                        uint32_t addr) {
    asm volatile("ldmatrix.sync.aligned.m8n8.x4.shared.b16 {%0,%1,%2,%3}, [%4];"
                 : "=r"(r0), "=r"(r1), "=r"(r2), "=r"(r3) : "r"(addr));
}
__device__ __forceinline__ void mma16816(float* c, const uint32_t* a, const uint32_t* b) {
    asm volatile(
        "mma.sync.aligned.m16n8k16.row.col.f32.bf16.bf16.f32 "
        "{%0,%1,%2,%3}, {%4,%5,%6,%7}, {%8,%9}, {%0,%1,%2,%3};"
        : "+f"(c[0]), "+f"(c[1]), "+f"(c[2]), "+f"(c[3])
        : "r"(a[0]), "r"(a[1]), "r"(a[2]), "r"(a[3]), "r"(b[0]), "r"(b[1]));
}

// ---------------- kernel 1: fused normalize + positive dots ----------------
// One block of 64 threads per batch row (R8 config: 69% occ, 7.9us).
__global__ void norm_kernel(const float* __restrict__ anchor,
                            const float* __restrict__ positive) {
    int i = blockIdx.x;
    int tid = threadIdx.x;                       // 0..63
    float4 a  = ((const float4*)(anchor  + (size_t)i * DIM))[tid];
    float4 p0 = ((const float4*)(positive + (size_t)i * 2 * DIM))[tid];
    float4 p1 = ((const float4*)(positive + (size_t)i * 2 * DIM + DIM))[tid];

    float s[5];
    s[0] = a.x * a.x + a.y * a.y + a.z * a.z + a.w * a.w;
    s[1] = p0.x * p0.x + p0.y * p0.y + p0.z * p0.z + p0.w * p0.w;
    s[2] = p1.x * p1.x + p1.y * p1.y + p1.z * p1.z + p1.w * p1.w;
    s[3] = a.x * p0.x + a.y * p0.y + a.z * p0.z + a.w * p0.w;
    s[4] = a.x * p1.x + a.y * p1.y + a.z * p1.z + a.w * p1.w;
#pragma unroll
    for (int k = 0; k < 5; k++)
#pragma unroll
        for (int o = 16; o; o >>= 1) s[k] += __shfl_down_sync(0xffffffffu, s[k], o);
    __shared__ float ws[2][5];
    if ((tid & 31) == 0)
#pragma unroll
        for (int k = 0; k < 5; k++) ws[tid >> 5][k] = s[k];
    __syncthreads();
    float na = ws[0][0] + ws[1][0];
    float n0 = ws[0][1] + ws[1][1];
    float n1 = ws[0][2] + ws[1][2];
    float d0 = ws[0][3] + ws[1][3];
    float d1 = ws[0][4] + ws[1][4];
    float ia = 1.0f / fmaxf(sqrtf(na), 1e-12f);
    float i0 = 1.0f / fmaxf(sqrtf(n0), 1e-12f);
    float i1 = 1.0f / fmaxf(sqrtf(n1), 1e-12f);

    if (tid == 0) {
        g_posdot[0][i] = d0 * ia * i0;
        g_posdot[1][i] = d1 * ia * i1;
        g_maxbits[0][i] = 0u;
        g_maxbits[1][i] = 0u;
    }

    uint2 pk;
    __nv_bfloat162 lo, hi;
    lo = __floats2bfloat162_rn(a.x * ia, a.y * ia);
    hi = __floats2bfloat162_rn(a.z * ia, a.w * ia);
    pk.x = *(uint32_t*)&lo; pk.y = *(uint32_t*)&hi;
    ((uint2*)(g_ab + (size_t)i * DIM))[tid] = pk;
    lo = __floats2bfloat162_rn(p0.x * i0, p0.y * i0);
    hi = __floats2bfloat162_rn(p0.z * i0, p0.w * i0);
    pk.x = *(uint32_t*)&lo; pk.y = *(uint32_t*)&hi;
    ((uint2*)(g_p0b + (size_t)i * DIM))[tid] = pk;
    lo = __floats2bfloat162_rn(p1.x * i1, p1.y * i1);
    hi = __floats2bfloat162_rn(p1.z * i1, p1.w * i1);
    pk.x = *(uint32_t*)&lo; pk.y = *(uint32_t*)&hi;
    ((uint2*)(g_p1b + (size_t)i * DIM))[tid] = pk;
}

// ---------------- kernel 2: bf16 mma.sync GEMM + masked max ----------------
// EXACT R8 mainloop: CTA tile 128x128, 8 warps (2m x 4n), warp tile 64x32,
// K chunks of 64, 2-stage cp.async pipeline, kb^(row&7) swizzle.
// Only delta vs R8: compact 1-D grid of 2576 blocks (no early-return CTAs):
//   [0,1024)    src1 dense, [1024,2048) src2 dense,
//   [2048,2576) src0 upper triangle (ctile >= rtile), col-fold when ctile>rtile.
#define TILE 128
#define CHUNK_BYTES (128 * 128)
#define SM_LABC 0
#define SM_LABR 512
#define SM_MAXR 1024
#define SM_MAXC 1536
#define SM_BUF  2048
#define SM_TOTAL (SM_BUF + 4 * CHUNK_BYTES)   // 67584

__global__ __launch_bounds__(256, 2) void gemm_max_kernel(const int* __restrict__ labels) {
    int bid = blockIdx.x;
    int src, rtile, ctile;
    if (bid < 2048) {
        src = 1 + (bid >> 10);
        int t = bid & 1023;
        rtile = t >> 5;
        ctile = t & 31;
    } else {
        src = 0;
        int t = bid - 2048;                     // 0..527 -> upper triangle (32 rows)
        int r = (int)(32.5f - sqrtf(1056.25f - 2.0f * (float)t));
        while (32 * r - r * (r - 1) / 2 > t) r--;
        while (32 * (r + 1) - (r + 1) * r / 2 <= t) r++;
        rtile = r;
        ctile = r + (t - (32 * r - r * (r - 1) / 2));
    }
    bool colfold = (src == 0) && (ctile > rtile);

    extern __shared__ char smem[];
    uint32_t smem_base = smem_u32(smem);
    int tid = threadIdx.x;
    int wid = tid >> 5, lane = tid & 31;
    int wm = wid >> 2;                 // 0..1
    int wn = wid & 3;                  // 0..3

    int colbase = ctile * TILE;
    int row0 = rtile * TILE;
    const __nv_bfloat16* Bmat = (src == 0) ? g_ab : (src == 1 ? g_p0b : g_p1b);

    if (tid < TILE) {
        *(int*)(smem + SM_LABC + tid * 4) = labels[colbase + tid];
        *(int*)(smem + SM_LABR + tid * 4) = labels[row0 + tid];
        *(unsigned*)(smem + SM_MAXR + tid * 4) = 0u;
        *(unsigned*)(smem + SM_MAXC + tid * 4) = 0u;
    }

    const char* gA = (const char*)(g_ab + (size_t)row0 * DIM);
    const char* gB = (const char*)(Bmat + (size_t)colbase * DIM);

    auto load_stage = [&](int s, int kc) {
        uint32_t abase = smem_base + SM_BUF + s * (2 * CHUNK_BYTES);
        uint32_t bbase = abase + CHUNK_BYTES;
#pragma unroll
        for (int i = 0; i < 4; i++) {
            int id = tid + i * 256;
            int row = id >> 3, kb = id & 7;
            uint32_t off = row * 128 + ((kb ^ (row & 7)) << 4);
            cp_async16(abase + off, gA + row * 512 + kc * 128 + kb * 16);
        }
#pragma unroll
        for (int i = 0; i < 4; i++) {
            int id = tid + i * 256;
            int row = id >> 3, kb = id & 7;
            uint32_t off = row * 128 + ((kb ^ (row & 7)) << 4);
            cp_async16(bbase + off, gB + row * 512 + kc * 128 + kb * 16);
        }
    };

    float acc[4][4][4];
#pragma unroll
    for (int i = 0; i < 4; i++)
#pragma unroll
        for (int j = 0; j < 4; j++)
#pragma unroll
            for (int k = 0; k < 4; k++) acc[i][j][k] = 0.f;

    int arow_lo = wm * 64 + (lane & 15);
    int brow_lo = wn * 32 + (lane & 7) + ((lane >> 4) << 3);
    int a_kb_lo = lane >> 4;
    int b_kb_lo = (lane >> 3) & 1;

    load_stage(0, 0);
    CP_COMMIT();

#pragma unroll
    for (int kc = 0; kc < 4; kc++) {
        if (kc < 3) load_stage((kc + 1) & 1, kc + 1);
        CP_COMMIT();
        CP_WAIT1();
        __syncthreads();

        uint32_t abase = smem_base + SM_BUF + (kc & 1) * (2 * CHUNK_BYTES);
        uint32_t bbase = abase + CHUNK_BYTES;
#pragma unroll
        for (int ks = 0; ks < 4; ks++) {
            uint32_t a[4][4];
            int akb = 2 * ks + a_kb_lo;
#pragma unroll
            for (int mf = 0; mf < 4; mf++) {
                int row = arow_lo + mf * 16;
                uint32_t addr = abase + row * 128 + ((akb ^ (row & 7)) << 4);
                ldsm_x4(a[mf][0], a[mf][1], a[mf][2], a[mf][3], addr);
            }
            uint32_t b[4][2];
            int bkb = 2 * ks + b_kb_lo;
#pragma unroll
            for (int nf2 = 0; nf2 < 2; nf2++) {
                int row = brow_lo + nf2 * 16;
                uint32_t addr = bbase + row * 128 + ((bkb ^ (row & 7)) << 4);
                uint32_t r0, r1, r2, r3;
                ldsm_x4(r0, r1, r2, r3, addr);
                b[nf2 * 2][0] = r0; b[nf2 * 2][1] = r1;
                b[nf2 * 2 + 1][0] = r2; b[nf2 * 2 + 1][1] = r3;
            }
#pragma unroll
            for (int mf = 0; mf < 4; mf++)
#pragma unroll
                for (int nfi = 0; nfi < 4; nfi++)
                    mma16816(acc[mf][nfi], a[mf], b[nfi]);
        }
        __syncthreads();
    }

    // ---- epilogue ----
    int g = lane >> 2, tg = lane & 3;
    const int* labC = (const int*)(smem + SM_LABC);
    const int* labR = (const int*)(smem + SM_LABR);
    unsigned* smaxr = (unsigned*)(smem + SM_MAXR);
    unsigned* smaxc = (unsigned*)(smem + SM_MAXC);

    // row-fold: masked max over this warp's 32 columns, per row
#pragma unroll
    for (int mf = 0; mf < 4; mf++) {
#pragma unroll
        for (int h = 0; h < 2; h++) {
            int row = wm * 64 + mf * 16 + g + h * 8;
            int rl = labR[row];
            float m = NEG_INF;
#pragma unroll
            for (int nfi = 0; nfi < 4; nfi++) {
                int col = wn * 32 + nfi * 8 + 2 * tg;
                if (labC[col] != rl)     m = fmaxf(m, acc[mf][nfi][h * 2 + 0]);
                if (labC[col + 1] != rl) m = fmaxf(m, acc[mf][nfi][h * 2 + 1]);
            }
            atomicMax(&smaxr[row], enc_f(m));
        }
    }

    // col-fold (mirror of symmetric tiles): masked max over this warp's 64 rows, per col
    if (colfold) {
#pragma unroll
        for (int nfi = 0; nfi < 4; nfi++) {
#pragma unroll
            for (int cpos = 0; cpos < 2; cpos++) {
                int col = wn * 32 + nfi * 8 + 2 * tg + cpos;
                int cl = labC[col];
                float m = NEG_INF;
#pragma unroll
                for (int mf = 0; mf < 4; mf++) {
#pragma unroll
                    for (int h = 0; h < 2; h++) {
                        int row = wm * 64 + mf * 16 + g + h * 8;
                        if (labR[row] != cl) m = fmaxf(m, acc[mf][nfi][h * 2 + cpos]);
                    }
                }
#pragma unroll
                for (int o = 4; o < 32; o <<= 1) m = fmaxf(m, __shfl_xor_sync(0xffffffffu, m, o));
                if (g == 0) atomicMax(&smaxc[col], enc_f(m));
            }
        }
    }

    __syncthreads();
    if (tid < TILE) {
        unsigned e = smaxr[tid];
        int grow = row0 + tid;
        if (src == 0) {
            atomicMax(&g_maxbits[0][grow], e);
            atomicMax(&g_maxbits[1][grow], e);
            if (colfold) {
                unsigned ec = smaxc[tid];
                int gcol = colbase + tid;
                atomicMax(&g_maxbits[0][gcol], ec);
                atomicMax(&g_maxbits[1][gcol], ec);
            }
        } else {
            atomicMax(&g_maxbits[src - 1][grow], e);
        }
    }
}

// ---------------- kernel 3: fused loss + reduction (single block) ----------------
__global__ void loss_kernel(float* __restrict__ out) {
    int tid = threadIdx.x;                 // 0..1023
    float s = 0.f;
#pragma unroll
    for (int k = 0; k < 8; k++) {
        int idx = tid + k * 1024;
        int v = idx >> 12;
        int i = idx & (BATCH - 1);
        float pd = g_posdot[v][i];
        float nd = dec_f(g_maxbits[v][i]);
        float pos = sqrtf(fmaxf(2.0f - 2.0f * pd, 1e-12f));
        float neg = sqrtf(fmaxf(2.0f - 2.0f * nd, 1e-12f));
        s += fmaxf(pos - neg + 1.0f, 0.0f);
    }
#pragma unroll
    for (int o = 16; o; o >>= 1) s += __shfl_down_sync(0xffffffffu, s, o);
    __shared__ float ws[32];
    if ((tid & 31) == 0) ws[tid >> 5] = s;
    __syncthreads();
    if (tid < 32) {
        float t = ws[tid];
#pragma unroll
        for (int o = 16; o; o >>= 1) t += __shfl_down_sync(0xffffffffu, t, o);
        if (tid == 0) out[0] = t * (1.0f / 8192.0f);
    }
}

// ---------------------------------------------------------------------------
extern "C" void kernel_launch(void* const* d_in, const int* in_sizes, int n_in,
                              void* d_out, int out_size) {
    const float* anchor = (const float*)d_in[0];
    const float* positive = (const float*)d_in[1];
    const int* labels = (const int*)d_in[2];

    cudaFuncSetAttribute(gemm_max_kernel, cudaFuncAttributeMaxDynamicSharedMemorySize, SM_TOTAL);

    norm_kernel<<<BATCH, 64>>>(anchor, positive);
    gemm_max_kernel<<<2576, 256, SM_TOTAL>>>(labels);
    loss_kernel<<<1, 1024>>>((float*)d_out);
}